// round 4
// baseline (speedup 1.0000x reference)
#include <cuda_runtime.h>
#include <cstdint>

#define HH 128
#define TT 512
#define BB 220
#define NROWS 660
#define NCLUSTER 66
#define RPC 10
#define RPG 5
#define NBLOCKS (NCLUSTER*2)
#define NTHREADS 256

typedef unsigned long long u64t;

// 660 * 512 * 128 floats = 173 MB scratch for all LSTM outputs
__device__ float g_hout[(size_t)NROWS * TT * HH];

__device__ __forceinline__ u64t ffma2(u64t a, u64t b, u64t c) {
  u64t d;
  asm("fma.rn.f32x2 %0, %1, %2, %3;" : "=l"(d) : "l"(a), "l"(b), "l"(c));
  return d;
}
__device__ __forceinline__ void unpack2(u64t v, float &lo, float &hi) {
  asm("mov.b64 {%0, %1}, %2;" : "=f"(lo), "=f"(hi) : "l"(v));
}
__device__ __forceinline__ float sigm(float x) {
  return __fdividef(1.f, 1.f + __expf(-x));
}
__device__ __forceinline__ float tanh_f(float x) {
  return __fdividef(2.f, 1.f + __expf(-2.f * x)) - 1.f;
}

// ---- cluster-scope mbarrier ops ----
__device__ __forceinline__ void mbar_arrive_remote_rel(unsigned raddr) {
  asm volatile("mbarrier.arrive.release.cluster.shared::cluster.b64 _, [%0];"
               :: "r"(raddr) : "memory");
}
__device__ __forceinline__ void mbar_wait_parity_acq(unsigned addr, unsigned parity) {
  asm volatile(
      "{\n\t.reg .pred P;\n\t"
      "WL_%=:\n\t"
      "mbarrier.try_wait.parity.acquire.cluster.shared::cta.b64 P, [%0], %1, 0x989680;\n\t"
      "@P bra.uni WD_%=;\n\t"
      "bra.uni WL_%=;\n\t"
      "WD_%=:\n\t}"
      :: "r"(addr), "r"(parity) : "memory");
}

// shared memory layout (float offsets)
#define SM_H   0        // [grp2][buf2][RPG][HH] = 2560
#define SM_X   2560     // [10 rows][512 t][2]   = 10240
#define SM_EX  12800    // [grp2][kh4][g4][RPG][64] = 10240
#define SM_MBAR 23040   // 4 x u64  (mbar[grp][pingpong])
#define SM_FLOATS 23048
#define SM_BYTES (SM_FLOATS*4)

extern __shared__ float smem_f[];

// partial gate sums for one row-group: each thread covers (j=q, k-quarter=kh)
__device__ __forceinline__ void fma_phase(const float* __restrict__ hb,
                                          const u64t wreg[4][16],
                                          float* __restrict__ exg,
                                          int q, int kh)
{
  u64t acc[4][RPG];
  #pragma unroll
  for (int g = 0; g < 4; ++g)
    #pragma unroll
    for (int r = 0; r < RPG; ++r) acc[g][r] = 0ull;

  const float* hbk = hb + kh*32;
  #pragma unroll
  for (int r = 0; r < RPG; ++r) {
    ulonglong2 hv[8];
    #pragma unroll
    for (int i = 0; i < 8; ++i)
      hv[i] = *(const ulonglong2*)(hbk + r*HH + i*4);
    #pragma unroll
    for (int g = 0; g < 4; ++g)
      #pragma unroll
      for (int i = 0; i < 8; ++i) {
        acc[g][r] = ffma2(wreg[g][2*i],   hv[i].x, acc[g][r]);
        acc[g][r] = ffma2(wreg[g][2*i+1], hv[i].y, acc[g][r]);
      }
  }
  #pragma unroll
  for (int g = 0; g < 4; ++g)
    #pragma unroll
    for (int r = 0; r < RPG; ++r) {
      float lo, hi; unpack2(acc[g][r], lo, hi);
      exg[((kh*4 + g)*RPG + r)*64 + q] = lo + hi;
    }
}

__global__ void __cluster_dims__(2,1,1) __launch_bounds__(NTHREADS, 1)
lstm_kernel(const float* __restrict__ x0p, const float* __restrict__ x1p,
            const float* __restrict__ x2p,
            const float* __restrict__ W_ih, const float* __restrict__ W_hh,
            const float* __restrict__ b_ih, const float* __restrict__ b_hh)
{
  float* h_sm = smem_f + SM_H;
  float* x_sm = smem_f + SM_X;
  float* ex_sm = smem_f + SM_EX;

  const int tid = threadIdx.x;
  unsigned rank;
  asm("mov.u32 %0, %%cluster_ctarank;" : "=r"(rank));
  const int cid  = blockIdx.x >> 1;
  const int row0 = cid * RPC;

  const int q  = tid & 63;          // j lane (FMA role)
  const int kh = tid >> 6;          // k quarter 0..3 (FMA role)
  const int jg = (int)rank*64 + q;

  // ---- W_hh in registers: 4 gates x 32 k ----
  u64t wreg[4][16];
  #pragma unroll
  for (int g = 0; g < 4; ++g) {
    const ulonglong2* wp =
        (const ulonglong2*)(W_hh + (size_t)(g*128 + jg)*HH + kh*32);
    #pragma unroll
    for (int i = 0; i < 8; ++i) {
      ulonglong2 v = wp[i];
      wreg[g][2*i]   = v.x;
      wreg[g][2*i+1] = v.y;
    }
  }

  // ---- preload x (first 2 of 4 coords) ----
  for (int idx = tid; idx < RPC*TT; idx += NTHREADS) {
    int r = idx >> 9, t = idx & (TT-1);
    int row = row0 + r;
    const float* xp; int b;
    if (row < BB)        { xp = x0p; b = row; }
    else if (row < 2*BB) { xp = x1p; b = row - BB; }
    else                 { xp = x2p; b = row - 2*BB; }
    float4 v = *(const float4*)(xp + ((size_t)b*TT + t)*4);
    x_sm[(r*TT + t)*2]     = v.x;
    x_sm[(r*TT + t)*2 + 1] = v.y;
  }
  // zero all h buffers
  for (int i = tid; i < 2*2*RPG*HH; i += NTHREADS) h_sm[i] = 0.f;

  // ---- mbarriers: [grp][pingpong] ----
  unsigned mbar_base = (unsigned)__cvta_generic_to_shared(smem_f + SM_MBAR);
  unsigned mbarL[2][2] = { { mbar_base,      mbar_base + 8  },
                           { mbar_base + 16, mbar_base + 24 } };
  if (tid == 0) {
    #pragma unroll
    for (int i = 0; i < 4; ++i)
      asm volatile("mbarrier.init.shared.b64 [%0], %1;"
                   :: "r"(mbar_base + i*8), "r"(256u) : "memory");
  }
  unsigned mbarR[2][2];
  #pragma unroll
  for (int g2 = 0; g2 < 2; ++g2)
    #pragma unroll
    for (int i = 0; i < 2; ++i)
      asm("mapa.shared::cluster.u32 %0, %1, %2;" : "=r"(mbarR[g2][i])
          : "r"(mbarL[g2][i]), "r"(rank ^ 1u));

  // ---- epilogue-role constants ----
  const int e_r1 = tid >> 6;
  const int e_jq = tid & 63;
  const bool has2 = (tid < 64);
  const int e_jg = (int)rank*64 + e_jq;
  float biasr[4], wi0[4], wi1[4];
  #pragma unroll
  for (int g = 0; g < 4; ++g) {
    int grow = g*128 + e_jg;
    biasr[g] = b_ih[grow] + b_hh[grow];
    wi0[g]   = W_ih[grow*2];
    wi1[g]   = W_ih[grow*2 + 1];
  }
  float c1[2] = {0.f, 0.f}, c2[2] = {0.f, 0.f};

  __syncthreads();
  asm volatile("barrier.cluster.arrive.aligned;" ::: "memory");
  asm volatile("barrier.cluster.wait.aligned;"   ::: "memory");

  for (int t = 0; t < TT; ++t) {
    const int buf = t & 1, nxt = buf ^ 1;
    const unsigned genp  = (unsigned)((t >> 1) & 1);        // parity of gen t on mbar[.][t&1]

    #pragma unroll
    for (int grp = 0; grp < 2; ++grp) {
      // group B: wait for peer's h_B(t-1) (gen t-1 on mbar[1][(t-1)&1])
      if (grp == 1 && t > 0)
        mbar_wait_parity_acq(mbarL[1][(t-1) & 1], (unsigned)(((t-1) >> 1) & 1));

      // ---- FMA partials for this group ----
      fma_phase(h_sm + (grp*2 + buf)*(RPG*HH), wreg,
                ex_sm + grp*(16*RPG*64), q, kh);
      __syncthreads();

      // ---- epilogue: all 256 threads ----
      const float* exg = ex_sm + grp*(16*RPG*64);
      float* hdst = h_sm + (grp*2 + nxt)*(RPG*HH);
      float* cs = (grp == 0) ? c1 : c2;
      float hout1, hout2 = 0.f;
      {
        int rr = e_r1;
        float x0 = x_sm[((grp*RPG + rr)*TT + t)*2];
        float x1 = x_sm[((grp*RPG + rr)*TT + t)*2 + 1];
        float gv[4];
        #pragma unroll
        for (int g = 0; g < 4; ++g) {
          float s = exg[((0*4 + g)*RPG + rr)*64 + e_jq]
                  + exg[((1*4 + g)*RPG + rr)*64 + e_jq]
                  + exg[((2*4 + g)*RPG + rr)*64 + e_jq]
                  + exg[((3*4 + g)*RPG + rr)*64 + e_jq];
          gv[g] = s + biasr[g] + wi0[g]*x0 + wi1[g]*x1;
        }
        float ig = sigm(gv[0]), fg = sigm(gv[1]);
        float gg = tanh_f(gv[2]), og = sigm(gv[3]);
        float c = fg * cs[0] + ig * gg;
        cs[0] = c;
        hout1 = og * tanh_f(c);
        int dst = (int)(hdst - h_sm) + rr*HH + e_jg;
        h_sm[dst] = hout1;
        unsigned laddr = (unsigned)__cvta_generic_to_shared(h_sm + dst);
        unsigned raddr;
        asm("mapa.shared::cluster.u32 %0, %1, %2;" : "=r"(raddr)
            : "r"(laddr), "r"(rank ^ 1u));
        asm volatile("st.shared::cluster.f32 [%0], %1;"
                     :: "r"(raddr), "f"(hout1) : "memory");
      }
      if (has2) {
        int rr = 4;
        float x0 = x_sm[((grp*RPG + rr)*TT + t)*2];
        float x1 = x_sm[((grp*RPG + rr)*TT + t)*2 + 1];
        float gv[4];
        #pragma unroll
        for (int g = 0; g < 4; ++g) {
          float s = exg[((0*4 + g)*RPG + rr)*64 + e_jq]
                  + exg[((1*4 + g)*RPG + rr)*64 + e_jq]
                  + exg[((2*4 + g)*RPG + rr)*64 + e_jq]
                  + exg[((3*4 + g)*RPG + rr)*64 + e_jq];
          gv[g] = s + biasr[g] + wi0[g]*x0 + wi1[g]*x1;
        }
        float ig = sigm(gv[0]), fg = sigm(gv[1]);
        float gg = tanh_f(gv[2]), og = sigm(gv[3]);
        float c = fg * cs[1] + ig * gg;
        cs[1] = c;
        hout2 = og * tanh_f(c);
        int dst = (int)(hdst - h_sm) + rr*HH + e_jg;
        h_sm[dst] = hout2;
        unsigned laddr = (unsigned)__cvta_generic_to_shared(h_sm + dst);
        unsigned raddr;
        asm("mapa.shared::cluster.u32 %0, %1, %2;" : "=r"(raddr)
            : "r"(laddr), "r"(rank ^ 1u));
        asm volatile("st.shared::cluster.f32 [%0], %1;"
                     :: "r"(raddr), "f"(hout2) : "memory");
      }
      // release-arrive on peer's mbar for this group/step (orders remote stores)
      mbar_arrive_remote_rel(mbarR[grp][buf]);

      // global h stores (off critical path)
      g_hout[((size_t)(row0 + grp*RPG + e_r1)*TT + t)*HH + e_jg] = hout1;
      if (has2)
        g_hout[((size_t)(row0 + grp*RPG + 4)*TT + t)*HH + e_jg] = hout2;
    }

    // wait for peer's h_A(t) before FMA_A(t+1): gen t on mbar[0][t&1]
    mbar_wait_parity_acq(mbarL[0][buf], genp);
  }

  asm volatile("barrier.cluster.arrive.aligned;" ::: "memory");
  asm volatile("barrier.cluster.wait.aligned;"   ::: "memory");
}

// ---------------- distance / gather kernel ----------------
__global__ void dist_kernel(const int* __restrict__ Lt, const int* __restrict__ La,
                            const int* __restrict__ Lf,
                            const int* __restrict__ tasl, const int* __restrict__ tfsl,
                            const int* __restrict__ asl,  const int* __restrict__ fsl,
                            float* __restrict__ out)
{
  int g = (blockIdx.x * blockDim.x + threadIdx.x) >> 5;
  int lane = threadIdx.x & 31;
  if (g >= 4840) return;
  int rowA, tA, rowB, tB;
  if (g < 220)       { int b = g;       rowA = b;  tA = max(Lt[b]-1, 0);   rowB = 220+b; tB = max(La[b]-1, 0); }
  else if (g < 440)  { int b = g-220;   rowA = b;  tA = max(Lt[b]-1, 0);   rowB = 440+b; tB = max(Lf[b]-1, 0); }
  else if (g < 2640) { int k = g-440;   int b = k/10; rowA = b; tA = max(tasl[k]-1, 0); rowB = 220+b; tB = max(asl[k]-1, 0); }
  else               { int k = g-2640;  int b = k/10; rowA = b; tA = max(tfsl[k]-1, 0); rowB = 440+b; tB = max(fsl[k]-1, 0); }

  const float4* pa = (const float4*)(g_hout + ((size_t)rowA*TT + tA)*HH);
  const float4* pb = (const float4*)(g_hout + ((size_t)rowB*TT + tB)*HH);
  float4 a = pa[lane], b4 = pb[lane];
  float dx = a.x-b4.x, dy = a.y-b4.y, dz = a.z-b4.z, dw = a.w-b4.w;
  float s = dx*dx + dy*dy + dz*dz + dw*dw;
  #pragma unroll
  for (int off = 16; off; off >>= 1) s += __shfl_xor_sync(0xffffffffu, s, off);
  if (lane == 0) out[g] = __expf(-__fsqrt_rn(s));
}

extern "C" void kernel_launch(void* const* d_in, const int* in_sizes, int n_in,
                              void* d_out, int out_size)
{
  const float* traj = (const float*)d_in[0];
  const int*   Lt   = (const int*)  d_in[1];
  const int*   tasl = (const int*)  d_in[2];
  const int*   tfsl = (const int*)  d_in[3];
  const float* anch = (const float*)d_in[4];
  const int*   La   = (const int*)  d_in[5];
  const int*   asl  = (const int*)  d_in[6];
  const float* fare = (const float*)d_in[7];
  const int*   Lf   = (const int*)  d_in[8];
  const int*   fsl  = (const int*)  d_in[9];
  const float* W_ih = (const float*)d_in[10];
  const float* W_hh = (const float*)d_in[11];
  const float* b_ih = (const float*)d_in[12];
  const float* b_hh = (const float*)d_in[13];

  cudaFuncSetAttribute(lstm_kernel, cudaFuncAttributeMaxDynamicSharedMemorySize,
                       SM_BYTES);
  lstm_kernel<<<NBLOCKS, NTHREADS, SM_BYTES>>>(traj, anch, fare, W_ih, W_hh,
                                               b_ih, b_hh);
  dist_kernel<<<(4840*32 + 255)/256, 256>>>(Lt, La, Lf, tasl, tfsl, asl, fsl,
                                            (float*)d_out);
}

// round 7
// speedup vs baseline: 1.1610x; 1.1610x over previous
#include <cuda_runtime.h>
#include <cstdint>

#define HH 128
#define TT 512
#define BB 220
#define NROWS 660
#define NCLUSTER 66
#define RPC 10
#define RPG 5
#define NBLOCKS (NCLUSTER*2)
#define NTHREADS 256

typedef unsigned long long u64t;

// 660 * 512 * 128 floats = 173 MB scratch for all LSTM outputs
__device__ float g_hout[(size_t)NROWS * TT * HH];

__device__ __forceinline__ u64t ffma2(u64t a, u64t b, u64t c) {
  u64t d;
  asm("fma.rn.f32x2 %0, %1, %2, %3;" : "=l"(d) : "l"(a), "l"(b), "l"(c));
  return d;
}
__device__ __forceinline__ u64t pack2(float lo, float hi) {
  u64t d;
  asm("mov.b64 %0, {%1, %2};" : "=l"(d) : "f"(lo), "f"(hi));
  return d;
}
__device__ __forceinline__ void unpack2(u64t v, float &lo, float &hi) {
  asm("mov.b64 {%0, %1}, %2;" : "=f"(lo), "=f"(hi) : "l"(v));
}
__device__ __forceinline__ float tanhap(float x) {
  float y;
  asm("tanh.approx.f32 %0, %1;" : "=f"(y) : "f"(x));
  return y;
}

// ---- cluster-scope mbarrier ops ----
__device__ __forceinline__ void mbar_arrive_remote_rel(unsigned raddr) {
  asm volatile("mbarrier.arrive.release.cluster.shared::cluster.b64 _, [%0];"
               :: "r"(raddr) : "memory");
}
__device__ __forceinline__ void mbar_wait_parity_acq(unsigned addr, unsigned parity) {
  asm volatile(
      "{\n\t.reg .pred P;\n\t"
      "WL_%=:\n\t"
      "mbarrier.try_wait.parity.acquire.cluster.shared::cta.b64 P, [%0], %1, 0x989680;\n\t"
      "@P bra.uni WD_%=;\n\t"
      "bra.uni WL_%=;\n\t"
      "WD_%=:\n\t}"
      :: "r"(addr), "r"(parity) : "memory");
}

// shared memory layout (float offsets)
#define SM_H   0        // [buf2][RPC][HH] = 2560
#define SM_X   2560     // [10 rows][512 t][2] = 10240
#define SM_EX  12800    // [g4][row10][q64][kh4] = 10240
#define SM_MBAR 23040   // 2 x u64
#define SM_FLOATS 23044
#define SM_BYTES (SM_FLOATS*4)

extern __shared__ float smem_f[];

__global__ void __cluster_dims__(2,1,1) __launch_bounds__(NTHREADS, 1)
lstm_kernel(const float* __restrict__ x0p, const float* __restrict__ x1p,
            const float* __restrict__ x2p,
            const float* __restrict__ W_ih, const float* __restrict__ W_hh,
            const float* __restrict__ b_ih, const float* __restrict__ b_hh)
{
  float* h_sm = smem_f + SM_H;
  float* x_sm = smem_f + SM_X;
  float* ex_sm = smem_f + SM_EX;

  const int tid = threadIdx.x;
  unsigned rank;
  asm("mov.u32 %0, %%cluster_ctarank;" : "=r"(rank));
  const int cid  = blockIdx.x >> 1;
  const int row0 = cid * RPC;

  const int q   = tid & 63;          // j lane (FMA role)
  const int kh  = tid >> 6;          // k quarter 0..3
  const int khp = kh ^ ((q >> 3) & 3);  // swizzled kh slot (conflict-free STS)
  const int jg  = (int)rank*64 + q;
  const bool is_epi = ((kh >> 1) == (int)rank);   // warps reading LOCAL h half

  // ---- W_hh in registers: 4 gates x 32 k, sigmoid gates prescaled by 0.5 ----
  u64t wreg[4][16];
  #pragma unroll
  for (int g = 0; g < 4; ++g) {
    const float sc = (g == 2) ? 1.f : 0.5f;
    const float4* wp =
        (const float4*)(W_hh + (size_t)(g*128 + jg)*HH + kh*32);
    #pragma unroll
    for (int i = 0; i < 8; ++i) {
      float4 v = wp[i];
      wreg[g][2*i]   = pack2(v.x*sc, v.y*sc);
      wreg[g][2*i+1] = pack2(v.z*sc, v.w*sc);
    }
  }

  // ---- preload x (first 2 of 4 coords) ----
  for (int idx = tid; idx < RPC*TT; idx += NTHREADS) {
    int r = idx >> 9, t = idx & (TT-1);
    int row = row0 + r;
    const float* xp; int b;
    if (row < BB)        { xp = x0p; b = row; }
    else if (row < 2*BB) { xp = x1p; b = row - BB; }
    else                 { xp = x2p; b = row - 2*BB; }
    float4 v = *(const float4*)(xp + ((size_t)b*TT + t)*4);
    x_sm[(r*TT + t)*2]     = v.x;
    x_sm[(r*TT + t)*2 + 1] = v.y;
  }
  // zero both h buffers
  for (int i = tid; i < 2*RPC*HH; i += NTHREADS) h_sm[i] = 0.f;

  // ---- mbarriers: ping-pong pair, count = 128 (peer's epi threads) ----
  unsigned mbar_base = (unsigned)__cvta_generic_to_shared(smem_f + SM_MBAR);
  unsigned mbarL[2] = { mbar_base, mbar_base + 8 };
  if (tid == 0) {
    asm volatile("mbarrier.init.shared.b64 [%0], %1;" :: "r"(mbarL[0]), "r"(128u) : "memory");
    asm volatile("mbarrier.init.shared.b64 [%0], %1;" :: "r"(mbarL[1]), "r"(128u) : "memory");
  }
  unsigned mbarR[2];
  #pragma unroll
  for (int i = 0; i < 2; ++i)
    asm("mapa.shared::cluster.u32 %0, %1, %2;" : "=r"(mbarR[i])
        : "r"(mbarL[i]), "r"(rank ^ 1u));

  // ---- epilogue-role constants (epi threads only; et in [0,128)) ----
  const int et   = tid & 127;
  const int e_jq = et & 63;
  const int e_rh = et >> 6;           // row-half: rows e_rh*5 .. e_rh*5+4
  const int e_jg = (int)rank*64 + e_jq;
  float biasr[4], wi0[4], wi1[4];
  #pragma unroll
  for (int g = 0; g < 4; ++g) {
    const float sc = (g == 2) ? 1.f : 0.5f;
    int grow = g*128 + e_jg;
    biasr[g] = (b_ih[grow] + b_hh[grow]) * sc;
    wi0[g]   = W_ih[grow*2] * sc;
    wi1[g]   = W_ih[grow*2 + 1] * sc;
  }
  float c_state[RPG];
  #pragma unroll
  for (int r = 0; r < RPG; ++r) c_state[r] = 0.f;

  __syncthreads();
  asm volatile("barrier.cluster.arrive.aligned;" ::: "memory");
  asm volatile("barrier.cluster.wait.aligned;"   ::: "memory");

  for (int t = 0; t < TT; ++t) {
    const int buf = t & 1, nxt = buf ^ 1;

    // remote-reading warps wait for peer's h(t) (exchange e = t-1)
    if (!is_epi && t > 0)
      mbar_wait_parity_acq(mbarL[(t-1) & 1], (unsigned)(((t-1) >> 1) & 1));

    // ---- FMA partials: 2 passes of 5 rows ----
    #pragma unroll
    for (int p = 0; p < 2; ++p) {
      u64t acc[4][RPG];
      #pragma unroll
      for (int g = 0; g < 4; ++g)
        #pragma unroll
        for (int r = 0; r < RPG; ++r) acc[g][r] = 0ull;

      const float* hb = h_sm + buf*(RPC*HH) + p*(RPG*HH) + kh*32;
      #pragma unroll
      for (int r = 0; r < RPG; ++r) {
        ulonglong2 hv[8];
        #pragma unroll
        for (int i = 0; i < 8; ++i)
          hv[i] = *(const ulonglong2*)(hb + r*HH + i*4);
        #pragma unroll
        for (int g = 0; g < 4; ++g)
          #pragma unroll
          for (int i = 0; i < 8; ++i) {
            acc[g][r] = ffma2(wreg[g][2*i],   hv[i].x, acc[g][r]);
            acc[g][r] = ffma2(wreg[g][2*i+1], hv[i].y, acc[g][r]);
          }
      }
      #pragma unroll
      for (int g = 0; g < 4; ++g)
        #pragma unroll
        for (int r = 0; r < RPG; ++r) {
          float lo, hi; unpack2(acc[g][r], lo, hi);
          ex_sm[((g*RPC + p*RPG + r)*64 + q)*4 + khp] = lo + hi;
        }
    }
    __syncthreads();

    // ---- epilogue: 128 local-half threads ----
    if (is_epi) {
      float hval[RPG];
      #pragma unroll
      for (int r = 0; r < RPG; ++r) {
        int rr = e_rh*RPG + r;
        float2 xv = *(const float2*)(x_sm + (rr*TT + t)*2);
        float gv[4];
        #pragma unroll
        for (int g = 0; g < 4; ++g) {
          float4 s4 = *(const float4*)(ex_sm + ((g*RPC + rr)*64 + e_jq)*4);
          gv[g] = (s4.x + s4.y) + (s4.z + s4.w)
                + biasr[g] + wi0[g]*xv.x + wi1[g]*xv.y;
        }
        float ig = 0.5f*tanhap(gv[0]) + 0.5f;
        float fg = 0.5f*tanhap(gv[1]) + 0.5f;
        float gg = tanhap(gv[2]);
        float og = 0.5f*tanhap(gv[3]) + 0.5f;
        float c  = fg * c_state[r] + ig * gg;
        c_state[r] = c;
        float h  = og * tanhap(c);
        hval[r] = h;

        int dst = nxt*(RPC*HH) + rr*HH + e_jg;
        h_sm[dst] = h;
        unsigned laddr = (unsigned)__cvta_generic_to_shared(h_sm + dst);
        unsigned raddr;
        asm("mapa.shared::cluster.u32 %0, %1, %2;" : "=r"(raddr)
            : "r"(laddr), "r"(rank ^ 1u));
        asm volatile("st.shared::cluster.f32 [%0], %1;"
                     :: "r"(raddr), "f"(h) : "memory");
      }
      // one release-arrive per epi thread (orders its remote stores)
      mbar_arrive_remote_rel(mbarR[buf]);

      // global h stores off the critical path
      #pragma unroll
      for (int r = 0; r < RPG; ++r)
        g_hout[((size_t)(row0 + e_rh*RPG + r)*TT + t)*HH + e_jg] = hval[r];
    }
    __syncthreads();
  }

  asm volatile("barrier.cluster.arrive.aligned;" ::: "memory");
  asm volatile("barrier.cluster.wait.aligned;"   ::: "memory");
}

// ---------------- distance / gather kernel ----------------
__global__ void dist_kernel(const int* __restrict__ Lt, const int* __restrict__ La,
                            const int* __restrict__ Lf,
                            const int* __restrict__ tasl, const int* __restrict__ tfsl,
                            const int* __restrict__ asl,  const int* __restrict__ fsl,
                            float* __restrict__ out)
{
  int g = (blockIdx.x * blockDim.x + threadIdx.x) >> 5;
  int lane = threadIdx.x & 31;
  if (g >= 4840) return;
  int rowA, tA, rowB, tB;
  if (g < 220)       { int b = g;       rowA = b;  tA = max(Lt[b]-1, 0);   rowB = 220+b; tB = max(La[b]-1, 0); }
  else if (g < 440)  { int b = g-220;   rowA = b;  tA = max(Lt[b]-1, 0);   rowB = 440+b; tB = max(Lf[b]-1, 0); }
  else if (g < 2640) { int k = g-440;   int b = k/10; rowA = b; tA = max(tasl[k]-1, 0); rowB = 220+b; tB = max(asl[k]-1, 0); }
  else               { int k = g-2640;  int b = k/10; rowA = b; tA = max(tfsl[k]-1, 0); rowB = 440+b; tB = max(fsl[k]-1, 0); }

  const float4* pa = (const float4*)(g_hout + ((size_t)rowA*TT + tA)*HH);
  const float4* pb = (const float4*)(g_hout + ((size_t)rowB*TT + tB)*HH);
  float4 a = pa[lane], b4 = pb[lane];
  float dx = a.x-b4.x, dy = a.y-b4.y, dz = a.z-b4.z, dw = a.w-b4.w;
  float s = dx*dx + dy*dy + dz*dz + dw*dw;
  #pragma unroll
  for (int off = 16; off; off >>= 1) s += __shfl_xor_sync(0xffffffffu, s, off);
  if (lane == 0) out[g] = __expf(-__fsqrt_rn(s));
}

extern "C" void kernel_launch(void* const* d_in, const int* in_sizes, int n_in,
                              void* d_out, int out_size)
{
  const float* traj = (const float*)d_in[0];
  const int*   Lt   = (const int*)  d_in[1];
  const int*   tasl = (const int*)  d_in[2];
  const int*   tfsl = (const int*)  d_in[3];
  const float* anch = (const float*)d_in[4];
  const int*   La   = (const int*)  d_in[5];
  const int*   asl  = (const int*)  d_in[6];
  const float* fare = (const float*)d_in[7];
  const int*   Lf   = (const int*)  d_in[8];
  const int*   fsl  = (const int*)  d_in[9];
  const float* W_ih = (const float*)d_in[10];
  const float* W_hh = (const float*)d_in[11];
  const float* b_ih = (const float*)d_in[12];
  const float* b_hh = (const float*)d_in[13];

  cudaFuncSetAttribute(lstm_kernel, cudaFuncAttributeMaxDynamicSharedMemorySize,
                       SM_BYTES);
  lstm_kernel<<<NBLOCKS, NTHREADS, SM_BYTES>>>(traj, anch, fare, W_ih, W_hh,
                                               b_ih, b_hh);
  dist_kernel<<<(4840*32 + 255)/256, 256>>>(Lt, La, Lf, tasl, tfsl, asl, fsl,
                                            (float*)d_out);
}

// round 8
// speedup vs baseline: 1.2797x; 1.1023x over previous
#include <cuda_runtime.h>
#include <cstdint>

#define HH 128
#define TT 512
#define BB 220
#define NROWS 660
#define NCLUSTER 74
#define RPC 9                 // rows per cluster (last cluster has 6 dummy rows)
#define NROWS_PAD (NCLUSTER*RPC)   // 666
#define NBLOCKS (NCLUSTER*2)
#define NTHREADS 256

typedef unsigned long long u64t;

// padded to 666 rows so dummy-row stores stay in bounds
__device__ float g_hout[(size_t)NROWS_PAD * TT * HH];

__device__ __forceinline__ u64t ffma2(u64t a, u64t b, u64t c) {
  u64t d;
  asm("fma.rn.f32x2 %0, %1, %2, %3;" : "=l"(d) : "l"(a), "l"(b), "l"(c));
  return d;
}
__device__ __forceinline__ u64t pack2(float lo, float hi) {
  u64t d;
  asm("mov.b64 %0, {%1, %2};" : "=l"(d) : "f"(lo), "f"(hi));
  return d;
}
__device__ __forceinline__ void unpack2(u64t v, float &lo, float &hi) {
  asm("mov.b64 {%0, %1}, %2;" : "=f"(lo), "=f"(hi) : "l"(v));
}
__device__ __forceinline__ float tanhap(float x) {
  float y;
  asm("tanh.approx.f32 %0, %1;" : "=f"(y) : "f"(x));
  return y;
}

// ---- cluster-scope mbarrier ops ----
__device__ __forceinline__ void mbar_arrive_remote_rel(unsigned raddr) {
  asm volatile("mbarrier.arrive.release.cluster.shared::cluster.b64 _, [%0];"
               :: "r"(raddr) : "memory");
}
__device__ __forceinline__ void mbar_wait_parity_acq(unsigned addr, unsigned parity) {
  asm volatile(
      "{\n\t.reg .pred P;\n\t"
      "WL_%=:\n\t"
      "mbarrier.try_wait.parity.acquire.cluster.shared::cta.b64 P, [%0], %1, 0x989680;\n\t"
      "@P bra.uni WD_%=;\n\t"
      "bra.uni WL_%=;\n\t"
      "WD_%=:\n\t}"
      :: "r"(addr), "r"(parity) : "memory");
}

// shared memory layout (float offsets)
#define SM_H   0                       // [buf2][RPC][HH] = 2304
#define SM_X   (2*RPC*HH)              // [RPC][TT][2]    = 9216
#define SM_EX  (SM_X + RPC*TT*2)       // [g4][row RPC][q64][kh4] = 9216
#define SM_MBAR (SM_EX + 4*RPC*64*4)   // 2 x u64
#define SM_FLOATS (SM_MBAR + 4)
#define SM_BYTES (SM_FLOATS*4)

extern __shared__ float smem_f[];

template <int NR>
__device__ __forceinline__ void fma_pass(const float* __restrict__ hb,
                                         const u64t wreg[4][16],
                                         float* __restrict__ exb,   // ex + row-offset
                                         int q, int khp)
{
  u64t acc[4][NR];
  #pragma unroll
  for (int g = 0; g < 4; ++g)
    #pragma unroll
    for (int r = 0; r < NR; ++r) acc[g][r] = 0ull;

  #pragma unroll
  for (int r = 0; r < NR; ++r) {
    ulonglong2 hv[8];
    #pragma unroll
    for (int i = 0; i < 8; ++i)
      hv[i] = *(const ulonglong2*)(hb + r*HH + i*4);
    #pragma unroll
    for (int g = 0; g < 4; ++g)
      #pragma unroll
      for (int i = 0; i < 8; ++i) {
        acc[g][r] = ffma2(wreg[g][2*i],   hv[i].x, acc[g][r]);
        acc[g][r] = ffma2(wreg[g][2*i+1], hv[i].y, acc[g][r]);
      }
  }
  #pragma unroll
  for (int g = 0; g < 4; ++g)
    #pragma unroll
    for (int r = 0; r < NR; ++r) {
      float lo, hi; unpack2(acc[g][r], lo, hi);
      exb[((g*RPC + r)*64 + q)*4 + khp] = lo + hi;
    }
}

__global__ void __cluster_dims__(2,1,1) __launch_bounds__(NTHREADS, 1)
lstm_kernel(const float* __restrict__ x0p, const float* __restrict__ x1p,
            const float* __restrict__ x2p,
            const float* __restrict__ W_ih, const float* __restrict__ W_hh,
            const float* __restrict__ b_ih, const float* __restrict__ b_hh)
{
  float* h_sm = smem_f + SM_H;
  float* x_sm = smem_f + SM_X;
  float* ex_sm = smem_f + SM_EX;

  const int tid = threadIdx.x;
  unsigned rank;
  asm("mov.u32 %0, %%cluster_ctarank;" : "=r"(rank));
  const int cid  = blockIdx.x >> 1;
  const int row0 = cid * RPC;

  const int q   = tid & 63;
  const int kh  = tid >> 6;
  const int khp = kh ^ ((q >> 3) & 3);   // swizzled STS slot
  const int jg  = (int)rank*64 + q;
  const bool is_epi = ((kh >> 1) == (int)rank);

  // ---- W_hh in registers: 4 gates x 32 k, sigmoid gates prescaled by 0.5 ----
  u64t wreg[4][16];
  #pragma unroll
  for (int g = 0; g < 4; ++g) {
    const float sc = (g == 2) ? 1.f : 0.5f;
    const float4* wp =
        (const float4*)(W_hh + (size_t)(g*128 + jg)*HH + kh*32);
    #pragma unroll
    for (int i = 0; i < 8; ++i) {
      float4 v = wp[i];
      wreg[g][2*i]   = pack2(v.x*sc, v.y*sc);
      wreg[g][2*i+1] = pack2(v.z*sc, v.w*sc);
    }
  }

  // ---- preload x (first 2 of 4 coords); zero for dummy rows ----
  for (int idx = tid; idx < RPC*TT; idx += NTHREADS) {
    int r = idx >> 9, t = idx & (TT-1);
    int row = row0 + r;
    float vx = 0.f, vy = 0.f;
    if (row < NROWS) {
      const float* xp; int b;
      if (row < BB)        { xp = x0p; b = row; }
      else if (row < 2*BB) { xp = x1p; b = row - BB; }
      else                 { xp = x2p; b = row - 2*BB; }
      float4 v = *(const float4*)(xp + ((size_t)b*TT + t)*4);
      vx = v.x; vy = v.y;
    }
    x_sm[(r*TT + t)*2]     = vx;
    x_sm[(r*TT + t)*2 + 1] = vy;
  }
  // zero both h buffers
  for (int i = tid; i < 2*RPC*HH; i += NTHREADS) h_sm[i] = 0.f;

  // ---- mbarriers: ping-pong pair, count = 128 (peer's epi threads) ----
  unsigned mbar_base = (unsigned)__cvta_generic_to_shared(smem_f + SM_MBAR);
  unsigned mbarL[2] = { mbar_base, mbar_base + 8 };
  if (tid == 0) {
    asm volatile("mbarrier.init.shared.b64 [%0], %1;" :: "r"(mbarL[0]), "r"(128u) : "memory");
    asm volatile("mbarrier.init.shared.b64 [%0], %1;" :: "r"(mbarL[1]), "r"(128u) : "memory");
  }
  unsigned mbarR[2];
  #pragma unroll
  for (int i = 0; i < 2; ++i)
    asm("mapa.shared::cluster.u32 %0, %1, %2;" : "=r"(mbarR[i])
        : "r"(mbarL[i]), "r"(rank ^ 1u));

  // ---- epilogue-role constants ----
  const int et   = tid & 127;
  const int e_jq = et & 63;
  const int e_rh = et >> 6;                    // 0: rows 0-4, 1: rows 5-8
  const int e_nr = 5 - e_rh;                   // 5 or 4 rows
  const int e_r0 = e_rh * 5;
  const int e_jg = (int)rank*64 + e_jq;
  float biasr[4], wi0[4], wi1[4];
  #pragma unroll
  for (int g = 0; g < 4; ++g) {
    const float sc = (g == 2) ? 1.f : 0.5f;
    int grow = g*128 + e_jg;
    biasr[g] = (b_ih[grow] + b_hh[grow]) * sc;
    wi0[g]   = W_ih[grow*2] * sc;
    wi1[g]   = W_ih[grow*2 + 1] * sc;
  }
  float c_state[5];
  #pragma unroll
  for (int r = 0; r < 5; ++r) c_state[r] = 0.f;

  __syncthreads();
  asm volatile("barrier.cluster.arrive.aligned;" ::: "memory");
  asm volatile("barrier.cluster.wait.aligned;"   ::: "memory");

  for (int t = 0; t < TT; ++t) {
    const int buf = t & 1, nxt = buf ^ 1;

    // remote-reading warps wait for peer's h(t)
    if (!is_epi && t > 0)
      mbar_wait_parity_acq(mbarL[(t-1) & 1], (unsigned)(((t-1) >> 1) & 1));

    // ---- FMA partials: pass of 5 rows + pass of 4 rows ----
    {
      const float* hb = h_sm + buf*(RPC*HH) + kh*32;
      fma_pass<5>(hb,          wreg, ex_sm,          q, khp);
      fma_pass<4>(hb + 5*HH,   wreg, ex_sm + 5*64*4, q, khp);
    }
    __syncthreads();

    // ---- epilogue: 128 local-half threads ----
    if (is_epi) {
      float hval[5];
      #pragma unroll
      for (int r = 0; r < 5; ++r) {
        if (r >= e_nr) break;
        int rr = e_r0 + r;
        float2 xv = *(const float2*)(x_sm + (rr*TT + t)*2);
        float gv[4];
        #pragma unroll
        for (int g = 0; g < 4; ++g) {
          float4 s4 = *(const float4*)(ex_sm + ((g*RPC + rr)*64 + e_jq)*4);
          gv[g] = (s4.x + s4.y) + (s4.z + s4.w)
                + biasr[g] + wi0[g]*xv.x + wi1[g]*xv.y;
        }
        float ig = 0.5f*tanhap(gv[0]) + 0.5f;
        float fg = 0.5f*tanhap(gv[1]) + 0.5f;
        float gg = tanhap(gv[2]);
        float og = 0.5f*tanhap(gv[3]) + 0.5f;
        float c  = fg * c_state[r] + ig * gg;
        c_state[r] = c;
        float h  = og * tanhap(c);
        hval[r] = h;

        int dst = nxt*(RPC*HH) + rr*HH + e_jg;
        h_sm[dst] = h;
        unsigned laddr = (unsigned)__cvta_generic_to_shared(h_sm + dst);
        unsigned raddr;
        asm("mapa.shared::cluster.u32 %0, %1, %2;" : "=r"(raddr)
            : "r"(laddr), "r"(rank ^ 1u));
        asm volatile("st.shared::cluster.f32 [%0], %1;"
                     :: "r"(raddr), "f"(h) : "memory");
      }
      mbar_arrive_remote_rel(mbarR[buf]);

      #pragma unroll
      for (int r = 0; r < 5; ++r) {
        if (r >= e_nr) break;
        g_hout[((size_t)(row0 + e_r0 + r)*TT + t)*HH + e_jg] = hval[r];
      }
    }
    __syncthreads();
  }

  asm volatile("barrier.cluster.arrive.aligned;" ::: "memory");
  asm volatile("barrier.cluster.wait.aligned;"   ::: "memory");
}

// ---------------- distance / gather kernel ----------------
__global__ void dist_kernel(const int* __restrict__ Lt, const int* __restrict__ La,
                            const int* __restrict__ Lf,
                            const int* __restrict__ tasl, const int* __restrict__ tfsl,
                            const int* __restrict__ asl,  const int* __restrict__ fsl,
                            float* __restrict__ out)
{
  int g = (blockIdx.x * blockDim.x + threadIdx.x) >> 5;
  int lane = threadIdx.x & 31;
  if (g >= 4840) return;
  int rowA, tA, rowB, tB;
  if (g < 220)       { int b = g;       rowA = b;  tA = max(Lt[b]-1, 0);   rowB = 220+b; tB = max(La[b]-1, 0); }
  else if (g < 440)  { int b = g-220;   rowA = b;  tA = max(Lt[b]-1, 0);   rowB = 440+b; tB = max(Lf[b]-1, 0); }
  else if (g < 2640) { int k = g-440;   int b = k/10; rowA = b; tA = max(tasl[k]-1, 0); rowB = 220+b; tB = max(asl[k]-1, 0); }
  else               { int k = g-2640;  int b = k/10; rowA = b; tA = max(tfsl[k]-1, 0); rowB = 440+b; tB = max(fsl[k]-1, 0); }

  const float4* pa = (const float4*)(g_hout + ((size_t)rowA*TT + tA)*HH);
  const float4* pb = (const float4*)(g_hout + ((size_t)rowB*TT + tB)*HH);
  float4 a = pa[lane], b4 = pb[lane];
  float dx = a.x-b4.x, dy = a.y-b4.y, dz = a.z-b4.z, dw = a.w-b4.w;
  float s = dx*dx + dy*dy + dz*dz + dw*dw;
  #pragma unroll
  for (int off = 16; off; off >>= 1) s += __shfl_xor_sync(0xffffffffu, s, off);
  if (lane == 0) out[g] = __expf(-__fsqrt_rn(s));
}

extern "C" void kernel_launch(void* const* d_in, const int* in_sizes, int n_in,
                              void* d_out, int out_size)
{
  const float* traj = (const float*)d_in[0];
  const int*   Lt   = (const int*)  d_in[1];
  const int*   tasl = (const int*)  d_in[2];
  const int*   tfsl = (const int*)  d_in[3];
  const float* anch = (const float*)d_in[4];
  const int*   La   = (const int*)  d_in[5];
  const int*   asl  = (const int*)  d_in[6];
  const float* fare = (const float*)d_in[7];
  const int*   Lf   = (const int*)  d_in[8];
  const int*   fsl  = (const int*)  d_in[9];
  const float* W_ih = (const float*)d_in[10];
  const float* W_hh = (const float*)d_in[11];
  const float* b_ih = (const float*)d_in[12];
  const float* b_hh = (const float*)d_in[13];

  cudaFuncSetAttribute(lstm_kernel, cudaFuncAttributeMaxDynamicSharedMemorySize,
                       SM_BYTES);
  lstm_kernel<<<NBLOCKS, NTHREADS, SM_BYTES>>>(traj, anch, fare, W_ih, W_hh,
                                               b_ih, b_hh);
  dist_kernel<<<(4840*32 + 255)/256, 256>>>(Lt, La, Lf, tasl, tfsl, asl, fsl,
                                            (float*)d_out);
}

// round 9
// speedup vs baseline: 1.8411x; 1.4387x over previous
#include <cuda_runtime.h>
#include <cuda_fp16.h>
#include <cstdint>

#define HH 128
#define TT 512
#define BB 220
#define NROWS 660
#define NCLUSTER 74
#define RPC 9
#define NROWS_PAD (NCLUSTER*RPC)   // 666
#define NBLOCKS (NCLUSTER*2)
#define NTHREADS 256

// h smem geometry (halfs): row stride 136 (=272B, conflict-free ldmatrix),
// plane stride 16*136=2176, buffer stride 2*2176=4352
#define HROW 136
#define HPL  (16*HROW)
#define HBUF (2*HPL)

// ex geometry (floats): [16 rows][264] ; item (row,jq) gates at row*264+jq*4
#define EXROW 264

// smem byte offsets
#define SM_H    0
#define SM_EX   (2*HBUF*2)                 // 17408
#define SM_X    (SM_EX + 16*EXROW*4)       // 17408+16896 = 34304
#define SM_MBAR (SM_X + RPC*TT*2*4)        // +36864 = 71168
#define SM_BYTES (SM_MBAR + 16)

__device__ float g_hout[(size_t)NROWS_PAD * TT * HH];

__device__ __forceinline__ float tanhap(float x) {
  float y;
  asm("tanh.approx.f32 %0, %1;" : "=f"(y) : "f"(x));
  return y;
}
__device__ __forceinline__ void mbar_arrive_remote_rel(unsigned raddr) {
  asm volatile("mbarrier.arrive.release.cluster.shared::cluster.b64 _, [%0];"
               :: "r"(raddr) : "memory");
}
__device__ __forceinline__ void mbar_wait_parity_acq(unsigned addr, unsigned parity) {
  asm volatile(
      "{\n\t.reg .pred P;\n\t"
      "WL_%=:\n\t"
      "mbarrier.try_wait.parity.acquire.cluster.shared::cta.b64 P, [%0], %1, 0x989680;\n\t"
      "@P bra.uni WD_%=;\n\t"
      "bra.uni WL_%=;\n\t"
      "WD_%=:\n\t}"
      :: "r"(addr), "r"(parity) : "memory");
}
__device__ __forceinline__ void ldsm4(uint32_t a[4], unsigned addr) {
  asm volatile("ldmatrix.sync.aligned.m8n8.x4.shared.b16 {%0,%1,%2,%3}, [%4];"
               : "=r"(a[0]), "=r"(a[1]), "=r"(a[2]), "=r"(a[3]) : "r"(addr));
}
__device__ __forceinline__ void mma16816(float c[4], const uint32_t a[4],
                                         const uint32_t b[2]) {
  asm volatile("mma.sync.aligned.m16n8k16.row.col.f32.f16.f16.f32 "
               "{%0,%1,%2,%3}, {%4,%5,%6,%7}, {%8,%9}, {%0,%1,%2,%3};"
               : "+f"(c[0]), "+f"(c[1]), "+f"(c[2]), "+f"(c[3])
               : "r"(a[0]), "r"(a[1]), "r"(a[2]), "r"(a[3]),
                 "r"(b[0]), "r"(b[1]));
}
__device__ __forceinline__ uint32_t packh2(float v0, float v1) {
  __half2 h = __floats2half2_rn(v0, v1);
  return *(uint32_t*)&h;
}

extern __shared__ char smem_c[];

__global__ void __cluster_dims__(2,1,1) __launch_bounds__(NTHREADS, 1)
lstm_kernel(const float* __restrict__ x0p, const float* __restrict__ x1p,
            const float* __restrict__ x2p,
            const float* __restrict__ W_ih, const float* __restrict__ W_hh,
            const float* __restrict__ b_ih, const float* __restrict__ b_hh)
{
  __half* h_sm = (__half*)(smem_c + SM_H);
  float*  ex   = (float*)(smem_c + SM_EX);
  float*  x_sm = (float*)(smem_c + SM_X);

  const int tid  = threadIdx.x;
  unsigned rank;
  asm("mov.u32 %0, %%cluster_ctarank;" : "=r"(rank));
  const int cid  = blockIdx.x >> 1;
  const int row0 = cid * RPC;

  const int w    = tid >> 5;          // warp 0..7: N-slice [w*32, w*32+32)
  const int lane = tid & 31;
  const int t4   = lane & 3;
  const int g8   = lane >> 2;

  // ---- persistent B fragments: [plane hi/lo][nt][seq s][pair] ----
  // seq s: s<4 -> local k-tiles (rank*4 + s), s>=4 -> remote ((rank^1)*4 + (s&3))
  uint32_t bhi[4][8][2], blo[4][8][2];
  {
    #pragma unroll
    for (int nt = 0; nt < 4; ++nt) {
      int n    = w*32 + nt*8 + g8;
      int gate = n & 3, jqw = n >> 2;
      int grow = gate*128 + (int)rank*64 + jqw;
      float sc = (gate == 2) ? 1.f : 0.5f;
      const float* wr = W_hh + (size_t)grow * HH;
      #pragma unroll
      for (int s = 0; s < 8; ++s) {
        int kt = ((s < 4) ? (int)rank : (int)(rank ^ 1u))*4 + (s & 3);
        #pragma unroll
        for (int pr = 0; pr < 2; ++pr) {
          int ks = kt*16 + 2*t4 + pr*8;
          float v0 = wr[ks] * sc, v1 = wr[ks+1] * sc;
          __half h0 = __float2half_rn(v0), h1 = __float2half_rn(v1);
          float  l0 = v0 - __half2float(h0), l1 = v1 - __half2float(h1);
          bhi[nt][s][pr] = packh2(__half2float(h0), __half2float(h1));
          blo[nt][s][pr] = packh2(l0, l1);
        }
      }
    }
  }

  // ---- preload x; zero h planes (both buffers) ----
  for (int idx = tid; idx < RPC*TT; idx += NTHREADS) {
    int r = idx >> 9, t = idx & (TT-1);
    int row = row0 + r;
    float vx = 0.f, vy = 0.f;
    if (row < NROWS) {
      const float* xp; int b;
      if (row < BB)        { xp = x0p; b = row; }
      else if (row < 2*BB) { xp = x1p; b = row - BB; }
      else                 { xp = x2p; b = row - 2*BB; }
      float4 v = *(const float4*)(xp + ((size_t)b*TT + t)*4);
      vx = v.x; vy = v.y;
    }
    x_sm[(r*TT + t)*2]     = vx;
    x_sm[(r*TT + t)*2 + 1] = vy;
  }
  for (int i = tid; i < 2*HBUF/2; i += NTHREADS)
    ((uint32_t*)h_sm)[i] = 0u;

  // ---- mbarriers: ping-pong, count 256 ----
  unsigned mbar_base = (unsigned)__cvta_generic_to_shared(smem_c + SM_MBAR);
  unsigned mbarL[2] = { mbar_base, mbar_base + 8 };
  if (tid == 0) {
    asm volatile("mbarrier.init.shared.b64 [%0], %1;" :: "r"(mbarL[0]), "r"(256u) : "memory");
    asm volatile("mbarrier.init.shared.b64 [%0], %1;" :: "r"(mbarL[1]), "r"(256u) : "memory");
  }
  unsigned mbarR[2];
  #pragma unroll
  for (int i = 0; i < 2; ++i)
    asm("mapa.shared::cluster.u32 %0, %1, %2;" : "=r"(mbarR[i])
        : "r"(mbarL[i]), "r"(rank ^ 1u));

  // ---- epilogue constants ----
  const int e_jq = tid & 63;
  const int e_G  = tid >> 6;
  const int e_r0 = (e_G == 0) ? 0 : (2*e_G + 1);   // {0,3,5,7}
  const int e_nr = (e_G == 0) ? 3 : 2;
  const int e_jg = (int)rank*64 + e_jq;
  float biasr[4], wi0[4], wi1[4];
  #pragma unroll
  for (int g = 0; g < 4; ++g) {
    const float sc = (g == 2) ? 1.f : 0.5f;
    int grow = g*128 + e_jg;
    biasr[g] = (b_ih[grow] + b_hh[grow]) * sc;
    wi0[g]   = W_ih[grow*2] * sc;
    wi1[g]   = W_ih[grow*2 + 1] * sc;
  }
  float c_state[3] = {0.f, 0.f, 0.f};

  const unsigned h_base = (unsigned)__cvta_generic_to_shared(h_sm);
  const unsigned a_lane_off = (unsigned)((lane & 15)*(HROW*2) + (lane >> 4)*16);

  __syncthreads();
  asm volatile("barrier.cluster.arrive.aligned;" ::: "memory");
  asm volatile("barrier.cluster.wait.aligned;"   ::: "memory");

  const int rank4a = (int)rank*4, rank4b = (int)(rank ^ 1u)*4;

  for (int t = 0; t < TT; ++t) {
    const int buf = t & 1, nxt = buf ^ 1;

    float cacc[4][4];
    #pragma unroll
    for (int nt = 0; nt < 4; ++nt)
      #pragma unroll
      for (int i = 0; i < 4; ++i) cacc[nt][i] = 0.f;

    const unsigned hb = h_base + (unsigned)buf*(HBUF*2) + a_lane_off;

    #pragma unroll
    for (int s = 0; s < 8; ++s) {
      if (s == 4 && t > 0)
        mbar_wait_parity_acq(mbarL[(t-1) & 1], (unsigned)(((t-1) >> 1) & 1));
      int kt = ((s < 4) ? rank4a : rank4b) + (s & 3);
      unsigned aaddr = hb + (unsigned)kt*32;
      uint32_t ahi[4], alo[4];
      ldsm4(ahi, aaddr);
      ldsm4(alo, aaddr + HPL*2);
      #pragma unroll
      for (int nt = 0; nt < 4; ++nt) {
        mma16816(cacc[nt], ahi, bhi[nt][s]);
        mma16816(cacc[nt], ahi, blo[nt][s]);
        mma16816(cacc[nt], alo, bhi[nt][s]);
      }
    }

    // ---- publish gates to ex: [row][jq*4 + gate] ----
    #pragma unroll
    for (int nt = 0; nt < 4; ++nt) {
      int jqw = w*8 + nt*2 + (t4 >> 1);
      int gb  = (t4 & 1)*2;
      float* p = ex + g8*EXROW + jqw*4 + gb;
      *(float2*)p               = make_float2(cacc[nt][0], cacc[nt][1]);
      *(float2*)(p + 8*EXROW)   = make_float2(cacc[nt][2], cacc[nt][3]);
    }
    __syncthreads();

    // ---- epilogue: all 256 threads, 2-3 items each ----
    {
      float hval[3];
      #pragma unroll
      for (int r = 0; r < 3; ++r) {
        if (r >= e_nr) break;
        int rr = e_r0 + r;
        float2 xv = *(const float2*)(x_sm + (rr*TT + t)*2);
        float4 g4 = *(const float4*)(ex + rr*EXROW + e_jq*4);
        float gi = g4.x + biasr[0] + wi0[0]*xv.x + wi1[0]*xv.y;
        float gf = g4.y + biasr[1] + wi0[1]*xv.x + wi1[1]*xv.y;
        float gg = g4.z + biasr[2] + wi0[2]*xv.x + wi1[2]*xv.y;
        float go = g4.w + biasr[3] + wi0[3]*xv.x + wi1[3]*xv.y;
        float ig = 0.5f*tanhap(gi) + 0.5f;
        float fg = 0.5f*tanhap(gf) + 0.5f;
        float gt = tanhap(gg);
        float og = 0.5f*tanhap(go) + 0.5f;
        float c  = fg * c_state[r] + ig * gt;
        c_state[r] = c;
        float h  = og * tanhap(c);
        hval[r] = h;

        __half hh = __float2half_rn(h);
        __half hl = __float2half_rn(h - __half2float(hh));
        int idx_hi = nxt*HBUF + rr*HROW + e_jg;
        int idx_lo = idx_hi + HPL;
        h_sm[idx_hi] = hh;
        h_sm[idx_lo] = hl;
        unsigned lhi = (unsigned)__cvta_generic_to_shared(h_sm + idx_hi);
        unsigned llo = (unsigned)__cvta_generic_to_shared(h_sm + idx_lo);
        unsigned rhi, rlo;
        asm("mapa.shared::cluster.u32 %0, %1, %2;" : "=r"(rhi) : "r"(lhi), "r"(rank ^ 1u));
        asm("mapa.shared::cluster.u32 %0, %1, %2;" : "=r"(rlo) : "r"(llo), "r"(rank ^ 1u));
        asm volatile("st.shared::cluster.b16 [%0], %1;"
                     :: "r"(rhi), "h"((unsigned short)__half_as_ushort(hh)) : "memory");
        asm volatile("st.shared::cluster.b16 [%0], %1;"
                     :: "r"(rlo), "h"((unsigned short)__half_as_ushort(hl)) : "memory");
      }
      mbar_arrive_remote_rel(mbarR[buf]);

      #pragma unroll
      for (int r = 0; r < 3; ++r) {
        if (r >= e_nr) break;
        g_hout[((size_t)(row0 + e_r0 + r)*TT + t)*HH + e_jg] = hval[r];
      }
    }
    __syncthreads();
  }

  asm volatile("barrier.cluster.arrive.aligned;" ::: "memory");
  asm volatile("barrier.cluster.wait.aligned;"   ::: "memory");
}

// ---------------- distance / gather kernel ----------------
__global__ void dist_kernel(const int* __restrict__ Lt, const int* __restrict__ La,
                            const int* __restrict__ Lf,
                            const int* __restrict__ tasl, const int* __restrict__ tfsl,
                            const int* __restrict__ asl,  const int* __restrict__ fsl,
                            float* __restrict__ out)
{
  int g = (blockIdx.x * blockDim.x + threadIdx.x) >> 5;
  int lane = threadIdx.x & 31;
  if (g >= 4840) return;
  int rowA, tA, rowB, tB;
  if (g < 220)       { int b = g;       rowA = b;  tA = max(Lt[b]-1, 0);   rowB = 220+b; tB = max(La[b]-1, 0); }
  else if (g < 440)  { int b = g-220;   rowA = b;  tA = max(Lt[b]-1, 0);   rowB = 440+b; tB = max(Lf[b]-1, 0); }
  else if (g < 2640) { int k = g-440;   int b = k/10; rowA = b; tA = max(tasl[k]-1, 0); rowB = 220+b; tB = max(asl[k]-1, 0); }
  else               { int k = g-2640;  int b = k/10; rowA = b; tA = max(tfsl[k]-1, 0); rowB = 440+b; tB = max(fsl[k]-1, 0); }

  const float4* pa = (const float4*)(g_hout + ((size_t)rowA*TT + tA)*HH);
  const float4* pb = (const float4*)(g_hout + ((size_t)rowB*TT + tB)*HH);
  float4 a = pa[lane], b4 = pb[lane];
  float dx = a.x-b4.x, dy = a.y-b4.y, dz = a.z-b4.z, dw = a.w-b4.w;
  float s = dx*dx + dy*dy + dz*dz + dw*dw;
  #pragma unroll
  for (int off = 16; off; off >>= 1) s += __shfl_xor_sync(0xffffffffu, s, off);
  if (lane == 0) out[g] = __expf(-__fsqrt_rn(s));
}

extern "C" void kernel_launch(void* const* d_in, const int* in_sizes, int n_in,
                              void* d_out, int out_size)
{
  const float* traj = (const float*)d_in[0];
  const int*   Lt   = (const int*)  d_in[1];
  const int*   tasl = (const int*)  d_in[2];
  const int*   tfsl = (const int*)  d_in[3];
  const float* anch = (const float*)d_in[4];
  const int*   La   = (const int*)  d_in[5];
  const int*   asl  = (const int*)  d_in[6];
  const float* fare = (const float*)d_in[7];
  const int*   Lf   = (const int*)  d_in[8];
  const int*   fsl  = (const int*)  d_in[9];
  const float* W_ih = (const float*)d_in[10];
  const float* W_hh = (const float*)d_in[11];
  const float* b_ih = (const float*)d_in[12];
  const float* b_hh = (const float*)d_in[13];

  cudaFuncSetAttribute(lstm_kernel, cudaFuncAttributeMaxDynamicSharedMemorySize,
                       SM_BYTES);
  lstm_kernel<<<NBLOCKS, NTHREADS, SM_BYTES>>>(traj, anch, fare, W_ih, W_hh,
                                               b_ih, b_hh);
  dist_kernel<<<(4840*32 + 255)/256, 256>>>(Lt, La, Lf, tasl, tfsl, asl, fsl,
                                            (float*)d_out);
}